// round 11
// baseline (speedup 1.0000x reference)
#include <cuda_runtime.h>
#include <cstdint>
#include <cstddef>

#define T_STEPS  100
#define BATCH    256
#define IN_DIM   1024
#define HID      2048
#define OUT_DIM  10
#define DECAY    0.9f
#define THRESH   1.0f
#define CH       32            // k-elements per chunk
#define AS_P     68            // As pitch (floats): 64 + 4
#define BS_P     132           // Bs pitch (floats): 128 + 4

// ---------------- device scratch (static, no allocations) ----------------
__device__ float g_X[(size_t)T_STEPS * BATCH * IN_DIM];   // transposed input: [T][B][IN]
__device__ float g_s1[2 * BATCH * HID];
__device__ float g_s2[2 * BATCH * HID];
__device__ float g_v1[BATCH * HID];
__device__ float g_v2[BATCH * HID];
__device__ float g_vout[BATCH * OUT_DIM];
__device__ float g_acc[BATCH * OUT_DIM];

// ---------------- transpose input_bins [B,IN_DIM,T] -> X [T, B*IN_DIM] ----------------
__global__ void transpose_kernel(const float* __restrict__ in)
{
    __shared__ float tile[32][33];
    int t0  = blockIdx.x * 32;
    int bi0 = blockIdx.y * 32;
    int tx = threadIdx.x, ty = threadIdx.y;

    #pragma unroll
    for (int r = ty; r < 32; r += 8) {
        int bi = bi0 + r, t = t0 + tx;
        tile[r][tx] = (t < T_STEPS) ? in[(size_t)bi * T_STEPS + t] : 0.0f;
    }
    __syncthreads();
    #pragma unroll
    for (int r = ty; r < 32; r += 8) {
        int t = t0 + r, bi = bi0 + tx;
        if (t < T_STEPS)
            g_X[(size_t)t * (BATCH * IN_DIM) + bi] = tile[tx][r];
    }
}

__global__ void zero_state_kernel()
{
    int i = blockIdx.x * 256 + threadIdx.x;
    if (i < BATCH * HID) { g_v1[i] = 0.0f; g_v2[i] = 0.0f; }
    if (i < BATCH * OUT_DIM) { g_vout[i] = 0.0f; g_acc[i] = 0.0f; }
}

// ---------------- fp32 GEMM tile (64m x 128n, 4x8/thread) + fused LIF ----------------
// Strict ascending-k single-accumulator scalar-FMA per output (bitwise == R7/R8).
__device__ __forceinline__ void gemm_tile(
    const float* __restrict__ A, const float* __restrict__ B,
    float* __restrict__ v, float* __restrict__ s,
    int K, int bx, int by, float* pool)
{
    float (*As)[AS_P] = (float (*)[AS_P])pool;             // [k][m]
    float (*Bs)[BS_P] = (float (*)[BS_P])(pool + CH * AS_P); // [k][n]

    int tid = threadIdx.x;
    int m0 = by * 64;
    int n0 = bx * 128;
    int r0 = (tid >> 4) << 2;       // 0..60 (m offset, 4 rows)
    int c0 = (tid & 15) << 2;       // 0..60 (n offset; cols c0 and c0+64)

    // loader mapping
    int rowA = tid & 63;            // A: row within tile
    int kA4  = (tid >> 6) << 2;     // A: k base (e=0 -> 0..12, e=1 -> +16)
    int kB   = tid >> 5;            // B: k row (e adds 8)
    int cB   = (tid & 31) << 2;     // B: col (float4)

    float acc[4][8];
    #pragma unroll
    for (int i = 0; i < 4; i++)
        #pragma unroll
        for (int j = 0; j < 8; j++) acc[i][j] = 0.0f;

    const int nch = K / CH;
    float4 aReg[2], bReg[4];

    // prefetch chunk 0
    #pragma unroll
    for (int e = 0; e < 2; e++)
        aReg[e] = *(const float4*)&A[(size_t)(m0 + rowA) * K + kA4 + e * 16];
    #pragma unroll
    for (int e = 0; e < 4; e++)
        bReg[e] = *(const float4*)&B[(size_t)(kB + e * 8) * HID + n0 + cB];
    // stage chunk 0
    #pragma unroll
    for (int e = 0; e < 2; e++) {
        int kl = kA4 + e * 16;
        As[kl + 0][rowA] = aReg[e].x;
        As[kl + 1][rowA] = aReg[e].y;
        As[kl + 2][rowA] = aReg[e].z;
        As[kl + 3][rowA] = aReg[e].w;
    }
    #pragma unroll
    for (int e = 0; e < 4; e++)
        *(float4*)&Bs[kB + e * 8][cB] = bReg[e];
    __syncthreads();

    for (int ch = 0; ch < nch; ch++) {
        // issue next-chunk global loads (latency hidden under compute)
        if (ch + 1 < nch) {
            int k0 = (ch + 1) * CH;
            #pragma unroll
            for (int e = 0; e < 2; e++)
                aReg[e] = *(const float4*)&A[(size_t)(m0 + rowA) * K + k0 + kA4 + e * 16];
            #pragma unroll
            for (int e = 0; e < 4; e++)
                bReg[e] = *(const float4*)&B[(size_t)(k0 + kB + e * 8) * HID + n0 + cB];
        }

        // compute: ascending k, one FMA per k per output
        #pragma unroll 4
        for (int k = 0; k < CH; k++) {
            float4 a4 = *(const float4*)&As[k][r0];
            float4 b0 = *(const float4*)&Bs[k][c0];
            float4 b1 = *(const float4*)&Bs[k][c0 + 64];
            float am[4] = { a4.x, a4.y, a4.z, a4.w };
            float bn[8] = { b0.x, b0.y, b0.z, b0.w, b1.x, b1.y, b1.z, b1.w };
            #pragma unroll
            for (int i = 0; i < 4; i++)
                #pragma unroll
                for (int j = 0; j < 8; j++)
                    acc[i][j] += am[i] * bn[j];
        }
        __syncthreads();

        if (ch + 1 < nch) {
            #pragma unroll
            for (int e = 0; e < 2; e++) {
                int kl = kA4 + e * 16;
                As[kl + 0][rowA] = aReg[e].x;
                As[kl + 1][rowA] = aReg[e].y;
                As[kl + 2][rowA] = aReg[e].z;
                As[kl + 3][rowA] = aReg[e].w;
            }
            #pragma unroll
            for (int e = 0; e < 4; e++)
                *(float4*)&Bs[kB + e * 8][cB] = bReg[e];
            __syncthreads();
        }
    }

    // fused LIF epilogue (elementwise; numerics identical to R7/R8)
    #pragma unroll
    for (int i = 0; i < 4; i++) {
        #pragma unroll
        for (int h = 0; h < 2; h++) {
            size_t base = (size_t)(m0 + r0 + i) * HID + (n0 + c0 + h * 64);
            float4 vv = *(const float4*)&v[base];
            float t0 = vv.x * DECAY + acc[i][h * 4 + 0];
            float t1 = vv.y * DECAY + acc[i][h * 4 + 1];
            float t2 = vv.z * DECAY + acc[i][h * 4 + 2];
            float t3 = vv.w * DECAY + acc[i][h * 4 + 3];
            bool p0 = t0 >= THRESH, p1 = t1 >= THRESH, p2 = t2 >= THRESH, p3 = t3 >= THRESH;
            float4 vn, sn;
            vn.x = p0 ? 0.0f : t0; vn.y = p1 ? 0.0f : t1;
            vn.z = p2 ? 0.0f : t2; vn.w = p3 ? 0.0f : t3;
            sn.x = p0 ? 1.0f : 0.0f; sn.y = p1 ? 1.0f : 0.0f;
            sn.z = p2 ? 1.0f : 0.0f; sn.w = p3 ? 1.0f : 0.0f;
            *(float4*)&v[base] = vn;
            *(float4*)&s[base] = sn;
        }
    }
}

// ---------------- fused step: [0,64)=L2(t), [64,128)=L1(t+1), [128,256)=OUT(t-1) ----------------
__global__ __launch_bounds__(256) void fused_step_kernel(
    const float* __restrict__ Xt,
    const float* __restrict__ W_ih,
    const float* __restrict__ W_hh,
    const float* __restrict__ W_ho,
    const float* __restrict__ s1r, float* __restrict__ s1w,
    const float* __restrict__ s2r, float* __restrict__ s2w,
    int doL1, int doL2, int doOUT)
{
    __shared__ float pool[CH * AS_P + CH * BS_P];   // 25600 B
    int blk = blockIdx.x;
    int tid = threadIdx.x;

    if (blk < 64) {                        // ---- L2(t): 16 n-tiles x 4 m-tiles
        if (!doL2) return;
        gemm_tile(s1r, W_hh, g_v2, s2w, HID, blk & 15, blk >> 4, pool);
    } else if (blk < 128) {                // ---- L1(t+1)
        if (!doL1) return;
        int b2 = blk - 64;
        gemm_tile(Xt, W_ih, g_v1, s1w, IN_DIM, b2 & 15, b2 >> 4, pool);
    } else {                               // ---- OUT(t-1)
        if (!doOUT) return;
        int group = tid >> 7;
        int lt    = tid & 127;
        int b     = (blk - 128) * 2 + group;

        float accv[OUT_DIM];
        #pragma unroll
        for (int o = 0; o < OUT_DIM; o++) accv[o] = 0.0f;

        const float* srow = s2r + (size_t)b * HID;
        for (int i = lt; i < HID; i += 128) {
            float sv = srow[i];
            if (sv != 0.0f) {
                #pragma unroll
                for (int o = 0; o < OUT_DIM; o++)
                    accv[o] += W_ho[(size_t)i * OUT_DIM + o];
            }
        }

        float* red = pool;                 // [2][OUT_DIM][128]
        #pragma unroll
        for (int o = 0; o < OUT_DIM; o++) red[(group * OUT_DIM + o) * 128 + lt] = accv[o];
        __syncthreads();

        for (int stride = 64; stride > 0; stride >>= 1) {
            if (lt < stride) {
                #pragma unroll
                for (int o = 0; o < OUT_DIM; o++)
                    red[(group * OUT_DIM + o) * 128 + lt] +=
                        red[(group * OUT_DIM + o) * 128 + lt + stride];
            }
            __syncthreads();
        }

        if (lt < OUT_DIM) {
            float cur = red[(group * OUT_DIM + lt) * 128];
            int idx = b * OUT_DIM + lt;
            float vv = g_vout[idx] * DECAY + cur;
            bool sp = (vv >= THRESH);
            g_vout[idx] = sp ? 0.0f : vv;
            if (sp) g_acc[idx] += 1.0f;
        }
    }
}

__global__ void finalize_kernel(float* __restrict__ out)
{
    int i = blockIdx.x * 256 + threadIdx.x;
    if (i < BATCH * OUT_DIM) out[i] = g_acc[i] * (1.0f / T_STEPS);
}

// ---------------- launch ----------------
extern "C" void kernel_launch(void* const* d_in, const int* in_sizes, int n_in,
                              void* d_out, int out_size)
{
    const float* in_bins = (const float*)d_in[0];   // [256,1024,100]
    const float* W_ih    = (const float*)d_in[1];   // [1024,2048]
    const float* W_hh    = (const float*)d_in[2];   // [1,2048,2048]
    const float* W_ho    = (const float*)d_in[3];   // [2048,10]
    float* out = (float*)d_out;

    float *X, *s1, *s2;
    cudaGetSymbolAddress((void**)&X,  g_X);
    cudaGetSymbolAddress((void**)&s1, g_s1);
    cudaGetSymbolAddress((void**)&s2, g_s2);

    // 1) transpose input
    {
        dim3 grid((T_STEPS + 31) / 32, (BATCH * IN_DIM) / 32);
        transpose_kernel<<<grid, dim3(32, 8)>>>(in_bins);
    }
    // 2) zero persistent state
    zero_state_kernel<<<(BATCH * HID + 255) / 256, 256>>>();

    // 3) software-pipelined time loop: call i runs L1(t=i), L2(t=i-1), OUT(t=i-2)
    for (int i = 0; i <= T_STEPS + 1; i++) {
        int ti = (i < T_STEPS) ? i : (T_STEPS - 1);
        const float* Xt  = X + (size_t)ti * BATCH * IN_DIM;
        float* s1w = s1 + (size_t)(i & 1) * BATCH * HID;
        const float* s1r = s1 + (size_t)((i - 1) & 1) * BATCH * HID;
        float* s2w = s2 + (size_t)((i - 1) & 1) * BATCH * HID;
        const float* s2r = s2 + (size_t)((i - 2) & 1) * BATCH * HID;
        int doL1  = (i < T_STEPS);
        int doL2  = (i >= 1) && (i <= T_STEPS);
        int doOUT = (i >= 2);
        fused_step_kernel<<<256, 256>>>(Xt, W_ih, W_hh, W_ho,
                                        s1r, s1w, s2r, s2w, doL1, doL2, doOUT);
    }

    // 4) finalize
    finalize_kernel<<<(BATCH * OUT_DIM + 255) / 256, 256>>>(out);
}

// round 12
// speedup vs baseline: 1.6734x; 1.6734x over previous
#include <cuda_runtime.h>
#include <cstdint>
#include <cstddef>

#define T_STEPS  100
#define BATCH    256
#define IN_DIM   1024
#define HID      2048
#define OUT_DIM  10
#define DECAY    0.9f
#define THRESH   1.0f
#define BS_P     260                     // Bs row pitch in floats (256 + 4)
#define POOL_FL  (2 * 32 * BS_P)         // two 32-k chunks of 256 n
#define SMEM_DYN (POOL_FL * 4 + 16 * 64) // 66560 + 1024 nibble scratch

// ---------------- device scratch (static, no allocations) ----------------
__device__ unsigned g_mX[(size_t)T_STEPS * BATCH * 32];  // input bits: [t][b][32 words]
__device__ unsigned g_m1[2][BATCH * 64];                 // layer1 spike bits (A for L2)
__device__ unsigned g_m2[2][BATCH * 64];                 // layer2 spike bits (for OUT)
__device__ float g_v1[BATCH * HID];
__device__ float g_v2[BATCH * HID];
__device__ float g_vout[BATCH * OUT_DIM];
__device__ float g_acc[BATCH * OUT_DIM];

// ---------------- helpers ----------------
__device__ __forceinline__ uint32_t smem_u32(const void* p) {
    uint32_t a;
    asm("{ .reg .u64 t; cvta.to.shared.u64 t, %1; cvt.u32.u64 %0, t; }" : "=r"(a) : "l"(p));
    return a;
}
__device__ __forceinline__ void cp16(uint32_t dst, const void* src) {
    asm volatile("cp.async.cg.shared.global [%0], [%1], 16;" :: "r"(dst), "l"(src) : "memory");
}
#define CP_COMMIT() asm volatile("cp.async.commit_group;" ::: "memory")

// ---------------- build input bitmasks: in[b][i][t] -> g_mX[t][b][i/32] ----------------
__global__ void maskify_kernel(const float* __restrict__ in)
{
    __shared__ float tile[32][33];
    int t0  = blockIdx.x * 32;
    int bi0 = blockIdx.y * 32;           // 32 consecutive (b,i); 1024%32==0 -> same b
    int tx = threadIdx.x, ty = threadIdx.y;

    #pragma unroll
    for (int r = ty; r < 32; r += 8) {
        int bi = bi0 + r, t = t0 + tx;
        tile[r][tx] = (t < T_STEPS) ? in[(size_t)bi * T_STEPS + t] : 0.0f;
    }
    __syncthreads();
    if (ty == 0) {
        int t = t0 + tx;
        if (t < T_STEPS) {
            unsigned w = 0;
            #pragma unroll
            for (int j = 0; j < 32; j++)
                if (tile[j][tx] != 0.0f) w |= (1u << j);
            int b  = bi0 >> 10;
            int iw = (bi0 & 1023) >> 5;
            g_mX[(size_t)t * (BATCH * 32) + b * 32 + iw] = w;
        }
    }
}

__global__ void zero_state_kernel()
{
    int i = blockIdx.x * 256 + threadIdx.x;
    if (i < BATCH * HID) { g_v1[i] = 0.0f; g_v2[i] = 0.0f; }
    if (i < BATCH * OUT_DIM) { g_vout[i] = 0.0f; g_acc[i] = 0.0f; }
}

// ---------------- sparse GEMM tile (16m x 256n) + fused LIF + mask output ----------------
// acc[n] = sum over active k (ascending) of W[k][n]; bitwise identical to the dense
// ascending-k fma chain since fma(0,w,acc)==acc and fma(1,w,acc)==acc+w exactly.
__device__ __forceinline__ void gemm_sparse(
    const unsigned* __restrict__ Am, int ws,      // A bitmask rows, words per row
    const float* __restrict__ B,                  // W [K][2048]
    float* __restrict__ v, unsigned* __restrict__ mOut,
    int K, int bx, int by, float* pool, unsigned char* nib)
{
    int tid  = threadIdx.x;
    int wid  = tid >> 5, lane = tid & 31;
    int m0   = by * 16, n0 = bx * 256;
    int m    = m0 + wid;
    int c0   = lane * 4;

    float acc[8] = {0.f,0.f,0.f,0.f,0.f,0.f,0.f,0.f};
    const int nch = K / 32;

    // stage mapping: 32 k-rows x 64 float4 cols, 512 threads x 4 cp16
    int kRow = tid >> 4;                 // 0..31
    int f0   = tid & 15;                 // float4 col base (+16e)
    uint32_t sb[2] = { smem_u32(pool), smem_u32(pool + 32 * BS_P) };

    #pragma unroll
    for (int e = 0; e < 4; e++)
        cp16(sb[0] + (uint32_t)(kRow * BS_P + (f0 + 16 * e) * 4) * 4,
             B + (size_t)kRow * HID + n0 + (f0 + 16 * e) * 4);
    CP_COMMIT();

    for (int ch = 0; ch < nch; ch++) {
        int b = ch & 1;
        const float* Bsb = pool + b * 32 * BS_P;

        if (ch + 1 < nch) {
            int k0 = (ch + 1) * 32;
            uint32_t dn = sb[b ^ 1];
            #pragma unroll
            for (int e = 0; e < 4; e++)
                cp16(dn + (uint32_t)(kRow * BS_P + (f0 + 16 * e) * 4) * 4,
                     B + (size_t)(k0 + kRow) * HID + n0 + (f0 + 16 * e) * 4);
            CP_COMMIT();
            asm volatile("cp.async.wait_group 1;" ::: "memory");
        } else {
            asm volatile("cp.async.wait_group 0;" ::: "memory");
        }
        __syncthreads();

        unsigned mask = Am[(size_t)m * ws + ch];
        while (mask) {
            int k = __ffs(mask) - 1;
            mask &= mask - 1;
            const float* row = Bsb + k * BS_P;
            float4 b0 = *(const float4*)&row[c0];
            float4 b1 = *(const float4*)&row[c0 + 128];
            acc[0] += b0.x; acc[1] += b0.y; acc[2] += b0.z; acc[3] += b0.w;
            acc[4] += b1.x; acc[5] += b1.y; acc[6] += b1.z; acc[7] += b1.w;
        }
        __syncthreads();   // all warps done reading buf b before it is re-staged
    }

    // ---- fused LIF epilogue + spike-bit packing ----
    unsigned nib0, nib1;
    {
        size_t base = (size_t)m * HID + n0 + c0;
        float4 vv = *(const float4*)&v[base];
        float t0 = vv.x * DECAY + acc[0];
        float t1 = vv.y * DECAY + acc[1];
        float t2 = vv.z * DECAY + acc[2];
        float t3 = vv.w * DECAY + acc[3];
        bool p0 = t0 >= THRESH, p1 = t1 >= THRESH, p2 = t2 >= THRESH, p3 = t3 >= THRESH;
        float4 vn;
        vn.x = p0 ? 0.0f : t0; vn.y = p1 ? 0.0f : t1;
        vn.z = p2 ? 0.0f : t2; vn.w = p3 ? 0.0f : t3;
        *(float4*)&v[base] = vn;
        nib0 = (unsigned)p0 | ((unsigned)p1 << 1) | ((unsigned)p2 << 2) | ((unsigned)p3 << 3);

        size_t base2 = base + 128;
        float4 vw = *(const float4*)&v[base2];
        float u0 = vw.x * DECAY + acc[4];
        float u1 = vw.y * DECAY + acc[5];
        float u2 = vw.z * DECAY + acc[6];
        float u3 = vw.w * DECAY + acc[7];
        bool q0 = u0 >= THRESH, q1 = u1 >= THRESH, q2 = u2 >= THRESH, q3 = u3 >= THRESH;
        float4 wn;
        wn.x = q0 ? 0.0f : u0; wn.y = q1 ? 0.0f : u1;
        wn.z = q2 ? 0.0f : u2; wn.w = q3 ? 0.0f : u3;
        *(float4*)&v[base2] = wn;
        nib1 = (unsigned)q0 | ((unsigned)q1 << 1) | ((unsigned)q2 << 2) | ((unsigned)q3 << 3);
    }
    nib[wid * 64 + lane]      = (unsigned char)nib0;   // half 0: n_local = lane*4
    nib[wid * 64 + 32 + lane] = (unsigned char)nib1;   // half 1: n_local = 128 + lane*4
    __syncwarp();
    if (lane < 8) {
        int half = lane >> 2, q4 = lane & 3;
        unsigned w = 0;
        #pragma unroll
        for (int q = 0; q < 8; q++)
            w |= (unsigned)nib[wid * 64 + half * 32 + q4 * 8 + q] << (4 * q);
        mOut[(size_t)m * 64 + (n0 >> 5) + lane] = w;
    }
}

// ---------------- fused step: [0,128)=L2(t), [128,256)=L1(t+1), [256,320)=OUT(t-1) ----------------
__global__ __launch_bounds__(512) void fused_step_kernel(
    const unsigned* __restrict__ mXt,
    const float* __restrict__ W_ih,
    const float* __restrict__ W_hh,
    const float* __restrict__ W_ho,
    const unsigned* __restrict__ m1r, unsigned* __restrict__ m1w,
    const unsigned* __restrict__ m2r, unsigned* __restrict__ m2w,
    int doL1, int doL2, int doOUT)
{
    extern __shared__ char dyn[];
    float* pool = (float*)dyn;
    unsigned char* nib = (unsigned char*)(dyn + POOL_FL * 4);
    int blk = blockIdx.x;
    int tid = threadIdx.x;

    if (blk < 128) {                       // ---- L2(t): m1 @ W_hh -> v2, m2
        if (!doL2) return;
        gemm_sparse(m1r, 64, W_hh, g_v2, m2w, HID, blk & 7, blk >> 3, pool, nib);
    } else if (blk < 256) {                // ---- L1(t+1): mX @ W_ih -> v1, m1
        if (!doL1) return;
        int b2 = blk - 128;
        gemm_sparse(mXt, 32, W_ih, g_v1, m1w, IN_DIM, b2 & 7, b2 >> 3, pool, nib);
    } else {                               // ---- OUT(t-1): mask-driven, order == validated kernel
        if (!doOUT) return;
        int group = tid >> 7;              // 0..3
        int lt    = tid & 127;
        int b     = (blk - 256) * 4 + group;

        float accv[OUT_DIM];
        #pragma unroll
        for (int o = 0; o < OUT_DIM; o++) accv[o] = 0.0f;

        const unsigned* mrow = m2r + (size_t)b * 64;
        #pragma unroll 4
        for (int j = 0; j < HID / 128; j++) {
            int i = lt + j * 128;
            unsigned w = mrow[i >> 5];
            if ((w >> (i & 31)) & 1u) {
                #pragma unroll
                for (int o = 0; o < OUT_DIM; o++)
                    accv[o] += W_ho[(size_t)i * OUT_DIM + o];
            }
        }

        float* red = pool;                 // [4][OUT_DIM][128]
        #pragma unroll
        for (int o = 0; o < OUT_DIM; o++) red[(group * OUT_DIM + o) * 128 + lt] = accv[o];
        __syncthreads();

        for (int stride = 64; stride > 0; stride >>= 1) {
            if (lt < stride) {
                #pragma unroll
                for (int o = 0; o < OUT_DIM; o++)
                    red[(group * OUT_DIM + o) * 128 + lt] +=
                        red[(group * OUT_DIM + o) * 128 + lt + stride];
            }
            __syncthreads();
        }

        if (lt < OUT_DIM) {
            float cur = red[(group * OUT_DIM + lt) * 128];
            int idx = b * OUT_DIM + lt;
            float vv = g_vout[idx] * DECAY + cur;
            bool sp = (vv >= THRESH);
            g_vout[idx] = sp ? 0.0f : vv;
            if (sp) g_acc[idx] += 1.0f;
        }
    }
}

__global__ void finalize_kernel(float* __restrict__ out)
{
    int i = blockIdx.x * 256 + threadIdx.x;
    if (i < BATCH * OUT_DIM) out[i] = g_acc[i] * (1.0f / T_STEPS);
}

// ---------------- launch ----------------
extern "C" void kernel_launch(void* const* d_in, const int* in_sizes, int n_in,
                              void* d_out, int out_size)
{
    const float* in_bins = (const float*)d_in[0];   // [256,1024,100]
    const float* W_ih    = (const float*)d_in[1];   // [1024,2048]
    const float* W_hh    = (const float*)d_in[2];   // [1,2048,2048]
    const float* W_ho    = (const float*)d_in[3];   // [2048,10]
    float* out = (float*)d_out;

    unsigned *mX, *m1, *m2;
    cudaGetSymbolAddress((void**)&mX, g_mX);
    cudaGetSymbolAddress((void**)&m1, g_m1);
    cudaGetSymbolAddress((void**)&m2, g_m2);

    cudaFuncSetAttribute(fused_step_kernel,
                         cudaFuncAttributeMaxDynamicSharedMemorySize, SMEM_DYN);

    // 1) build input bitmasks
    {
        dim3 grid((T_STEPS + 31) / 32, (BATCH * IN_DIM) / 32);
        maskify_kernel<<<grid, dim3(32, 8)>>>(in_bins);
    }
    // 2) zero persistent state
    zero_state_kernel<<<(BATCH * HID + 255) / 256, 256>>>();

    // 3) software-pipelined time loop: call i runs L1(t=i), L2(t=i-1), OUT(t=i-2)
    for (int i = 0; i <= T_STEPS + 1; i++) {
        int ti = (i < T_STEPS) ? i : (T_STEPS - 1);
        const unsigned* mXt = mX + (size_t)ti * (BATCH * 32);
        unsigned* m1w = m1 + (size_t)(i & 1) * (BATCH * 64);
        const unsigned* m1r = m1 + (size_t)((i - 1) & 1) * (BATCH * 64);
        unsigned* m2w = m2 + (size_t)((i - 1) & 1) * (BATCH * 64);
        const unsigned* m2r = m2 + (size_t)((i - 2) & 1) * (BATCH * 64);
        int doL1  = (i < T_STEPS);
        int doL2  = (i >= 1) && (i <= T_STEPS);
        int doOUT = (i >= 2);
        fused_step_kernel<<<320, 512, SMEM_DYN>>>(mXt, W_ih, W_hh, W_ho,
                                                  m1r, m1w, m2r, m2w,
                                                  doL1, doL2, doOUT);
    }

    // 4) finalize
    finalize_kernel<<<(BATCH * OUT_DIM + 255) / 256, 256>>>(out);
}